// round 7
// baseline (speedup 1.0000x reference)
#include <cuda_runtime.h>

// DenseWarpLayer: bilinear warp, N=8, H=512, W=512, C=32 fp32.
// R7: R6's 32x8 tile walk + distance-1 software pipeline: row r+1's four
// gather LDG.128s are issued BEFORE row r is computed/stored, so every warp
// keeps ~512B of DRAM reads outstanding continuously (duty cycle ~100% vs
// ~50% in R4/R6). Costs a second live payload set (~46 regs, 5 blocks/SM,
// 40 warps) — trading occupancy for in-flight bytes, which the R6 post-
// mortem identified as the binding constraint (bandwidth-delay product).
// Plain stores (stcs measured slightly worse in R2/R3/R5). 32-bit indexing.

#define N_ 8
#define H_ 512
#define W_ 512
#define C4_ 8u            // 32 channels = 8 float4
#define ROW4 (W_ * C4_)   // float4 per image row = 4096
#define TILE_W 32u
#define TILE_H 8u
#define TILES_X (W_ / TILE_W)              // 16
#define TILES_PER_IMG (TILES_X * (H_ / TILE_H))  // 1024

__device__ __forceinline__ unsigned query(unsigned x, unsigned y, unsigned nH,
                                          const float2 fl, unsigned c4,
                                          float& ax, float& ay)
{
    const float qy = (float)y - fl.x;
    const float qx = (float)x - fl.y;

    float fyf = floorf(qy);
    float fxf = floorf(qx);
    fyf = fminf(fmaxf(fyf, 0.0f), (float)(H_ - 2));
    fxf = fminf(fmaxf(fxf, 0.0f), (float)(W_ - 2));

    ay = fminf(fmaxf(qy - fyf, 0.0f), 1.0f);
    ax = fminf(fmaxf(qx - fxf, 0.0f), 1.0f);

    return ((nH + (unsigned)(int)fyf) * W_ + (unsigned)(int)fxf) * C4_ + c4;
}

__device__ __forceinline__ float4 bilerp4(const float4 tl, const float4 tr,
                                          const float4 bl, const float4 br,
                                          const float ax, const float ay)
{
    float4 r; float top, bot;
    top = tl.x + ax * (tr.x - tl.x); bot = bl.x + ax * (br.x - bl.x);
    r.x = top + ay * (bot - top);
    top = tl.y + ax * (tr.y - tl.y); bot = bl.y + ax * (br.y - bl.y);
    r.y = top + ay * (bot - top);
    top = tl.z + ax * (tr.z - tl.z); bot = bl.z + ax * (br.z - bl.z);
    r.z = top + ay * (bot - top);
    top = tl.w + ax * (tr.w - tl.w); bot = bl.w + ax * (br.w - bl.w);
    r.w = top + ay * (bot - top);
    return r;
}

__global__ __launch_bounds__(256)
void dense_warp_kernel(const float* __restrict__ image,
                       const float* __restrict__ flow,
                       float* __restrict__ out)
{
    const unsigned tid  = threadIdx.x;
    const unsigned c4   = tid & 7u;        // channel quad
    const unsigned col  = tid >> 3;        // column within tile, 0..31

    const unsigned blk  = blockIdx.x;
    const unsigned n    = blk >> 10;                 // / TILES_PER_IMG
    const unsigned rem  = blk & (TILES_PER_IMG - 1);
    const unsigned ty   = rem >> 4;                  // / TILES_X
    const unsigned tx   = rem & (TILES_X - 1);

    const unsigned x    = tx * TILE_W + col;
    const unsigned y0   = ty * TILE_H;
    const unsigned nH   = n * H_;
    const unsigned pix0 = nH * (unsigned)W_ + y0 * W_ + x;

    const float2* fl2  = reinterpret_cast<const float2*>(flow);
    const float4* img4 = reinterpret_cast<const float4*>(image);
    float4*       out4 = reinterpret_cast<float4*>(out);

    // ---- prologue: flow + gathers for row 0 in flight
    float2 fln = __ldg(fl2 + pix0);                  // flow row 0
    float2 fl  = fln;
    fln = __ldg(fl2 + pix0 + W_);                    // flow row 1

    float axc, ayc;
    unsigned rb = query(x, y0, nH, fl, c4, axc, ayc);
    float4 tl = __ldg(img4 + rb);
    float4 tr = __ldg(img4 + rb + C4_);
    float4 bl = __ldg(img4 + rb + ROW4);
    float4 br = __ldg(img4 + rb + ROW4 + C4_);

    #pragma unroll 1
    for (unsigned r = 0; r < TILE_H - 1u; ++r) {
        // take current payload
        const float4 ctl = tl, ctr = tr, cbl = bl, cbr = br;
        const float cax = axc, cay = ayc;
        const unsigned pix = pix0 + r * W_;

        // issue NEXT row's gathers before computing this row
        const float2 flr = fln;
        if (r + 2u < TILE_H)
            fln = __ldg(fl2 + pix + 2u * W_);
        rb = query(x, y0 + r + 1u, nH, flr, c4, axc, ayc);
        tl = __ldg(img4 + rb);
        tr = __ldg(img4 + rb + C4_);
        bl = __ldg(img4 + rb + ROW4);
        br = __ldg(img4 + rb + ROW4 + C4_);

        // compute + store current row (covers next row's load latency)
        out4[pix * C4_ + c4] = bilerp4(ctl, ctr, cbl, cbr, cax, cay);
    }

    // ---- epilogue: last row
    const unsigned pix = pix0 + (TILE_H - 1u) * W_;
    out4[pix * C4_ + c4] = bilerp4(tl, tr, bl, br, axc, ayc);
}

extern "C" void kernel_launch(void* const* d_in, const int* in_sizes, int n_in,
                              void* d_out, int out_size)
{
    const float* image = (const float*)d_in[0];
    const float* flow  = (const float*)d_in[1];
    float* out = (float*)d_out;

    // N * TILES_PER_IMG = 8192 blocks, 256 threads each
    dense_warp_kernel<<<8192, 256>>>(image, flow, out);
}

// round 8
// speedup vs baseline: 1.0459x; 1.0459x over previous
#include <cuda_runtime.h>
#include <cstdint>

// DenseWarpLayer: bilinear warp, N=8, H=512, W=512, C=32 fp32.
// R8: R6's 32x8 tile walk, but the 4 corner gathers per row go through
// cp.async.ca (LDGSTS) into a double-buffered per-thread smem slot, issued
// TWO rows ahead. In-flight read bytes are decoupled from the register file
// (the R2/R3/R7 lesson: register-ILP always loses to occupancy here), so each
// warp keeps ~1KB outstanding continuously vs ~512B at 50% duty before.
// No __syncthreads: every thread consumes only the data it fetched itself;
// per-group completion via cp.async.commit_group / wait_group.

#define N_ 8
#define H_ 512
#define W_ 512
#define C4_ 8u            // 32 channels = 8 float4
#define ROW4 (W_ * C4_)   // float4 per image row = 4096
#define TILE_W 32u
#define TILE_H 8u
#define TILES_X 16u
#define TILES_PER_IMG 1024u

__device__ __forceinline__ void cp16(uint32_t saddr, const void* gptr)
{
    asm volatile("cp.async.ca.shared.global [%0], [%1], 16;"
                 :: "r"(saddr), "l"(gptr));
}

__device__ __forceinline__ float4 bilerp4(const float4 tl, const float4 tr,
                                          const float4 bl, const float4 br,
                                          const float ax, const float ay)
{
    float4 r; float top, bot;
    top = tl.x + ax * (tr.x - tl.x); bot = bl.x + ax * (br.x - bl.x);
    r.x = top + ay * (bot - top);
    top = tl.y + ax * (tr.y - tl.y); bot = bl.y + ax * (br.y - bl.y);
    r.y = top + ay * (bot - top);
    top = tl.z + ax * (tr.z - tl.z); bot = bl.z + ax * (br.z - bl.z);
    r.z = top + ay * (bot - top);
    top = tl.w + ax * (tr.w - tl.w); bot = bl.w + ax * (br.w - bl.w);
    r.w = top + ay * (bot - top);
    return r;
}

__global__ __launch_bounds__(256)
void dense_warp_kernel(const float* __restrict__ image,
                       const float* __restrict__ flow,
                       float* __restrict__ out)
{
    // [stage][corner][tid] : lanes 0..7 of a phase cover 128 contiguous bytes
    // -> conflict-free LDS.128 and coalesced cp.async smem side.
    __shared__ float4 sbuf[2][4][256];

    const unsigned tid = threadIdx.x;
    const unsigned c4  = tid & 7u;        // channel quad
    const unsigned col = tid >> 3;        // column within tile

    const unsigned blk = blockIdx.x;
    const unsigned n   = blk >> 10;                  // / TILES_PER_IMG
    const unsigned rem = blk & (TILES_PER_IMG - 1u);
    const unsigned ty  = rem >> 4;                   // / TILES_X
    const unsigned tx  = rem & (TILES_X - 1u);

    const unsigned x    = tx * TILE_W + col;
    const unsigned y0   = ty * TILE_H;
    const unsigned nH   = n * H_;
    const unsigned pix0 = (nH + y0) * W_ + x;

    const float2* fl2  = reinterpret_cast<const float2*>(flow);
    const float4* img4 = reinterpret_cast<const float4*>(image);
    float4*       out4 = reinterpret_cast<float4*>(out);

    const uint32_t sbase =
        (uint32_t)__cvta_generic_to_shared(&sbuf[0][0][tid]);

    float axs[2], ays[2];   // constant-indexed after unroll -> registers

    // issue row (y0+r)'s 4 corner gathers into stage st, record alphas
    #define ISSUE_ROW(r_, st_, fl_)                                          \
    do {                                                                     \
        const float qy = (float)(y0 + (r_)) - (fl_).x;                       \
        const float qx = (float)x - (fl_).y;                                 \
        float fyf = floorf(qy), fxf = floorf(qx);                            \
        fyf = fminf(fmaxf(fyf, 0.0f), (float)(H_ - 2));                      \
        fxf = fminf(fmaxf(fxf, 0.0f), (float)(W_ - 2));                      \
        ays[st_] = fminf(fmaxf(qy - fyf, 0.0f), 1.0f);                       \
        axs[st_] = fminf(fmaxf(qx - fxf, 0.0f), 1.0f);                       \
        const unsigned rb =                                                  \
            ((nH + (unsigned)(int)fyf) * W_ + (unsigned)(int)fxf) * C4_ + c4;\
        const uint32_t s0 = sbase + (uint32_t)(st_) * (4u * 256u * 16u);     \
        cp16(s0,                  img4 + rb);                                \
        cp16(s0 + 1u * 256u * 16u, img4 + rb + C4_);                         \
        cp16(s0 + 2u * 256u * 16u, img4 + rb + ROW4);                        \
        cp16(s0 + 3u * 256u * 16u, img4 + rb + ROW4 + C4_);                  \
        asm volatile("cp.async.commit_group;");                              \
    } while (0)

    // ---- prologue: rows 0 and 1 in flight, flow for row 2 loading
    const float2 flA = __ldg(fl2 + pix0);
    const float2 flB = __ldg(fl2 + pix0 + W_);
    ISSUE_ROW(0u, 0u, flA);
    ISSUE_ROW(1u, 1u, flB);
    float2 fln = __ldg(fl2 + pix0 + 2u * W_);

    #pragma unroll
    for (unsigned r = 0; r < TILE_H; ++r) {
        const unsigned st = r & 1u;

        // row r's group complete (<=1 newer group may still be pending)
        if (r < TILE_H - 1u) asm volatile("cp.async.wait_group 1;");
        else                 asm volatile("cp.async.wait_group 0;");

        // consume own slot (conflict-free LDS.128 x4)
        const float4 tl = sbuf[st][0][tid];
        const float4 tr = sbuf[st][1][tid];
        const float4 bl = sbuf[st][2][tid];
        const float4 br = sbuf[st][3][tid];
        const float ax = axs[st], ay = ays[st];

        // refill this stage with row r+2 (LDS above precedes overwrite;
        // async write lands >=1 global round-trip later)
        if (r + 2u < TILE_H) {
            const float2 fl = fln;
            if (r + 3u < TILE_H)
                fln = __ldg(fl2 + pix0 + (r + 3u) * W_);
            ISSUE_ROW(r + 2u, st, fl);
        }

        out4[(pix0 + r * W_) * C4_ + c4] = bilerp4(tl, tr, bl, br, ax, ay);
    }
    #undef ISSUE_ROW
}

extern "C" void kernel_launch(void* const* d_in, const int* in_sizes, int n_in,
                              void* d_out, int out_size)
{
    const float* image = (const float*)d_in[0];
    const float* flow  = (const float*)d_in[1];
    float* out = (float*)d_out;

    // N * TILES_PER_IMG = 8192 blocks, 256 threads each
    dense_warp_kernel<<<8192, 256>>>(image, flow, out);
}

// round 9
// speedup vs baseline: 1.2063x; 1.1534x over previous
#include <cuda_runtime.h>

// DenseWarpLayer: bilinear warp, N=8, H=512, W=512, C=32 fp32.
// R9: R4's proven inner body (8 threads/pixel full-128B-line warp accesses,
// 2 sequential pixels/thread with both flow loads hoisted, 32 regs,
// 8 blocks/SM) wrapped in a PERSISTENT grid-stride loop sized to exactly one
// wave (1184 blocks = 148 SMs x 8). R4 ran 27.7 block-waves with ramp/drain
// at every boundary (achieved occ 82.9% vs 100% theoretical); a single
// resident wave keeps all 64 warps/SM eligible for the whole kernel, which
// is the only remaining lever (R7/R8 falsified the in-flight-bytes theory;
// R2/R3/R7/R8 falsified register-ILP; R6 falsified L2-hit latency).

#define N_ 8
#define H_ 512
#define W_ 512
#define C4_ 8u            // 32 channels = 8 float4
#define ROW4 (W_ * C4_)   // float4 per image row = 4096
#define NBLOCKS 1184u     // 148 SMs * 8 blocks -> exactly one wave
#define NTHREADS (NBLOCKS * 256u)
#define NTASKS 8388608u   // N*H*W*8 / 2 pixel-pair tasks

__device__ __forceinline__ unsigned gather_base(unsigned pix, unsigned c4,
                                                const float2 fl,
                                                float& ax, float& ay)
{
    const unsigned w = pix & (W_ - 1);
    const unsigned h = (pix >> 9) & (H_ - 1);
    const unsigned n = pix >> 18;

    const float qy = (float)h - fl.x;
    const float qx = (float)w - fl.y;

    float fyf = floorf(qy);
    float fxf = floorf(qx);
    fyf = fminf(fmaxf(fyf, 0.0f), (float)(H_ - 2));
    fxf = fminf(fmaxf(fxf, 0.0f), (float)(W_ - 2));

    ay = fminf(fmaxf(qy - fyf, 0.0f), 1.0f);
    ax = fminf(fmaxf(qx - fxf, 0.0f), 1.0f);

    return ((n * H_ + (unsigned)(int)fyf) * W_ + (unsigned)(int)fxf) * C4_ + c4;
}

__device__ __forceinline__ float4 bilerp4(const float4 tl, const float4 tr,
                                          const float4 bl, const float4 br,
                                          const float ax, const float ay)
{
    float4 r; float top, bot;
    top = tl.x + ax * (tr.x - tl.x); bot = bl.x + ax * (br.x - bl.x);
    r.x = top + ay * (bot - top);
    top = tl.y + ax * (tr.y - tl.y); bot = bl.y + ax * (br.y - bl.y);
    r.y = top + ay * (bot - top);
    top = tl.z + ax * (tr.z - tl.z); bot = bl.z + ax * (br.z - bl.z);
    r.z = top + ay * (bot - top);
    top = tl.w + ax * (tr.w - tl.w); bot = bl.w + ax * (br.w - bl.w);
    r.w = top + ay * (bot - top);
    return r;
}

__device__ __forceinline__ void do_pixel(const float4* __restrict__ img4,
                                         float4* __restrict__ out4,
                                         unsigned pix, unsigned c4,
                                         const float2 fl)
{
    float ax, ay;
    const unsigned rb = gather_base(pix, c4, fl, ax, ay);

    const float4 tl = __ldg(img4 + rb);
    const float4 tr = __ldg(img4 + rb + C4_);
    const float4 bl = __ldg(img4 + rb + ROW4);
    const float4 br = __ldg(img4 + rb + ROW4 + C4_);

    out4[pix * C4_ + c4] = bilerp4(tl, tr, bl, br, ax, ay);
}

__global__ __launch_bounds__(256, 8)
void dense_warp_kernel(const float* __restrict__ image,
                       const float* __restrict__ flow,
                       float* __restrict__ out)
{
    const float2* fl2  = reinterpret_cast<const float2*>(flow);
    const float4* img4 = reinterpret_cast<const float4*>(image);
    float4*       out4 = reinterpret_cast<float4*>(out);

    const unsigned tid0 = blockIdx.x * 256u + threadIdx.x;

    // grid-stride over pixel-pair tasks; same task->pixel decode as R4:
    // warp = 4 pixel-slots x 8 quads; a task covers pixels pix0 and pix0+4,
    // so every warp-level LDG.128/STG.128 touches 4 full 128B lines.
    #pragma unroll 1
    for (unsigned task = tid0; task < NTASKS; task += NTHREADS) {
        const unsigned c4   = task & 7u;
        const unsigned slot = task >> 3;
        const unsigned grp  = slot >> 2;
        const unsigned r    = slot & 3u;
        const unsigned pix0 = grp * 8u + r;
        const unsigned pix1 = pix0 + 4u;

        // hoist BOTH flow loads: flow1 latency hides under pixel0's work
        const float2 fl0 = __ldg(fl2 + pix0);
        const float2 fl1 = __ldg(fl2 + pix1);

        do_pixel(img4, out4, pix0, c4, fl0);
        do_pixel(img4, out4, pix1, c4, fl1);
    }
}

extern "C" void kernel_launch(void* const* d_in, const int* in_sizes, int n_in,
                              void* d_out, int out_size)
{
    const float* image = (const float*)d_in[0];
    const float* flow  = (const float*)d_in[1];
    float* out = (float*)d_out;

    dense_warp_kernel<<<NBLOCKS, 256>>>(image, flow, out);
}

// round 10
// speedup vs baseline: 1.2335x; 1.0226x over previous
#include <cuda_runtime.h>

// DenseWarpLayer: bilinear warp, N=8, H=512, W=512, C=32 fp32.
// R10 = R9 (persistent single-wave grid, 8 threads/pixel full-line warp
// accesses, 2 sequential pixels/task, 32 regs / 8 blocks / 64 warps) plus
// ZERO-REGISTER flow prefetch: each iteration issues prefetch.global.L1 for
// the NEXT grid-stride iteration's flow line (constant +75776-pixel offset;
// both pixels' float2 flows live in the same 128B line). This removes one of
// the two serial DRAM round-trips per task (flow ~600cyc -> L1/L2 hit)
// without spending payload registers — the only lever class that hasn't
// been falsified (R2/R3/R7/R8: register-ILP loses; R6: L2-hit conversion
// neutral; R9: occupancy 95% neutral).

#define N_ 8
#define H_ 512
#define W_ 512
#define C4_ 8u            // 32 channels = 8 float4
#define ROW4 (W_ * C4_)   // float4 per image row = 4096
#define NBLOCKS 1184u     // 148 SMs * 8 blocks -> exactly one wave
#define NTHREADS (NBLOCKS * 256u)
#define NTASKS 8388608u   // N*H*W*8 / 2 pixel-pair tasks
#define PIX_STRIDE 75776u // pixel offset between successive iterations
#define MAX_PIX 2097151u  // N*H*W - 1

__device__ __forceinline__ unsigned gather_base(unsigned pix, unsigned c4,
                                                const float2 fl,
                                                float& ax, float& ay)
{
    const unsigned w = pix & (W_ - 1);
    const unsigned h = (pix >> 9) & (H_ - 1);
    const unsigned n = pix >> 18;

    const float qy = (float)h - fl.x;
    const float qx = (float)w - fl.y;

    float fyf = floorf(qy);
    float fxf = floorf(qx);
    fyf = fminf(fmaxf(fyf, 0.0f), (float)(H_ - 2));
    fxf = fminf(fmaxf(fxf, 0.0f), (float)(W_ - 2));

    ay = fminf(fmaxf(qy - fyf, 0.0f), 1.0f);
    ax = fminf(fmaxf(qx - fxf, 0.0f), 1.0f);

    return ((n * H_ + (unsigned)(int)fyf) * W_ + (unsigned)(int)fxf) * C4_ + c4;
}

__device__ __forceinline__ float4 bilerp4(const float4 tl, const float4 tr,
                                          const float4 bl, const float4 br,
                                          const float ax, const float ay)
{
    float4 r; float top, bot;
    top = tl.x + ax * (tr.x - tl.x); bot = bl.x + ax * (br.x - bl.x);
    r.x = top + ay * (bot - top);
    top = tl.y + ax * (tr.y - tl.y); bot = bl.y + ax * (br.y - bl.y);
    r.y = top + ay * (bot - top);
    top = tl.z + ax * (tr.z - tl.z); bot = bl.z + ax * (br.z - bl.z);
    r.z = top + ay * (bot - top);
    top = tl.w + ax * (tr.w - tl.w); bot = bl.w + ax * (br.w - bl.w);
    r.w = top + ay * (bot - top);
    return r;
}

__device__ __forceinline__ void do_pixel(const float4* __restrict__ img4,
                                         float4* __restrict__ out4,
                                         unsigned pix, unsigned c4,
                                         const float2 fl)
{
    float ax, ay;
    const unsigned rb = gather_base(pix, c4, fl, ax, ay);

    const float4 tl = __ldg(img4 + rb);
    const float4 tr = __ldg(img4 + rb + C4_);
    const float4 bl = __ldg(img4 + rb + ROW4);
    const float4 br = __ldg(img4 + rb + ROW4 + C4_);

    out4[pix * C4_ + c4] = bilerp4(tl, tr, bl, br, ax, ay);
}

__global__ __launch_bounds__(256, 8)
void dense_warp_kernel(const float* __restrict__ image,
                       const float* __restrict__ flow,
                       float* __restrict__ out)
{
    const float2* fl2  = reinterpret_cast<const float2*>(flow);
    const float4* img4 = reinterpret_cast<const float4*>(image);
    float4*       out4 = reinterpret_cast<float4*>(out);

    const unsigned tid0 = blockIdx.x * 256u + threadIdx.x;

    #pragma unroll 1
    for (unsigned task = tid0; task < NTASKS; task += NTHREADS) {
        const unsigned c4   = task & 7u;
        const unsigned slot = task >> 3;
        const unsigned grp  = slot >> 2;
        const unsigned r    = slot & 3u;
        const unsigned pix0 = grp * 8u + r;
        const unsigned pix1 = pix0 + 4u;

        // prefetch NEXT iteration's flow line (covers both its pixels'
        // float2 values: +32B apart, always same 128B line). Clamped so the
        // final iteration prefetches a valid in-buffer address.
        {
            const unsigned npix = min(pix0 + PIX_STRIDE, MAX_PIX);
            asm volatile("prefetch.global.L1 [%0];" :: "l"(fl2 + npix));
        }

        // this iteration's flows (L1/L2 hits after warm-up)
        const float2 fl0 = __ldg(fl2 + pix0);
        const float2 fl1 = __ldg(fl2 + pix1);

        do_pixel(img4, out4, pix0, c4, fl0);
        do_pixel(img4, out4, pix1, c4, fl1);
    }
}

extern "C" void kernel_launch(void* const* d_in, const int* in_sizes, int n_in,
                              void* d_out, int out_size)
{
    const float* image = (const float*)d_in[0];
    const float* flow  = (const float*)d_in[1];
    float* out = (float*)d_out;

    dense_warp_kernel<<<NBLOCKS, 256>>>(image, flow, out);
}